// round 15
// baseline (speedup 1.0000x reference)
#include <cuda_runtime.h>
#include <cuda_fp16.h>
#include <stdint.h>

#define TILE    128
#define THREADS 256
#define XPAD    72   // halves per row: 64 data + 8 pad

// ---- dynamic smem layout (bytes) ----
#define OFF_XSRAW 0          // float[128][64]  = 32768
#define OFF_XS    32768      // half [128][72]  = 18432
#define OFF_WS1   51200      // half [64][72]   =  9216
#define OFF_WS2   60416      // half [32][72]   =  4608
#define OFF_B1    65024      // float[64]
#define OFF_B2    65280      // float[32]
#define OFF_WO    65408      // float[48]
#define OFF_MFD   65600      // float[128]
#define OFF_US    66112      // int[2][128]
#define OFF_IS    67136      // int[2][128]
#define OFF_BOS   68160      // float
#define SMEM_TOTAL 68224

__device__ __forceinline__ void mma16816(float c[4], const uint32_t a[4],
                                         uint32_t b0, uint32_t b1) {
    asm volatile(
        "mma.sync.aligned.m16n8k16.row.col.f32.f16.f16.f32 "
        "{%0,%1,%2,%3}, {%4,%5,%6,%7}, {%8,%9}, {%0,%1,%2,%3};"
        : "+f"(c[0]), "+f"(c[1]), "+f"(c[2]), "+f"(c[3])
        : "r"(a[0]), "r"(a[1]), "r"(a[2]), "r"(a[3]), "r"(b0), "r"(b1));
}

__device__ __forceinline__ void cp_async16(uint32_t dst, const void* src) {
    asm volatile("cp.async.cg.shared.global [%0], [%1], 16;\n" :: "r"(dst), "l"(src));
}

__global__ __launch_bounds__(THREADS, 3)   // 85-reg cap
void neumf_fused(const int* __restrict__ user, const int* __restrict__ item,
                 const float* __restrict__ mf_u, const float* __restrict__ mf_i,
                 const float* __restrict__ mlp_u, const float* __restrict__ mlp_i,
                 const float* __restrict__ W1, const float* __restrict__ b1,
                 const float* __restrict__ W2, const float* __restrict__ b2,
                 const float* __restrict__ Wo, const float* __restrict__ bo,
                 float* __restrict__ out, int n, int ntiles)
{
    extern __shared__ char smem[];
    float  (*XsRaw)[64]  = (float (*)[64]) (smem + OFF_XSRAW);
    __half (*Xs)[XPAD]   = (__half(*)[XPAD])(smem + OFF_XS);
    __half (*Ws1)[XPAD]  = (__half(*)[XPAD])(smem + OFF_WS1);
    __half (*Ws2)[XPAD]  = (__half(*)[XPAD])(smem + OFF_WS2);
    float* b1s  = (float*)(smem + OFF_B1);
    float* b2s  = (float*)(smem + OFF_B2);
    float* Wos  = (float*)(smem + OFF_WO);
    float* mfd  = (float*)(smem + OFF_MFD);
    int*   usb  = (int*)  (smem + OFF_US);
    int*   isb  = (int*)  (smem + OFF_IS);
    float* bosp = (float*)(smem + OFF_BOS);

    const int t     = threadIdx.x;
    const int lane8 = t & 7;       // float4 chunk within 128B row
    const int rowg  = t >> 3;      // 0..31

    // ---- Prologue: weights + tile-0 indices, then launch tile-0 cp.async ----
    for (int idx = t; idx < 64 * 64; idx += THREADS) {
        int k = idx >> 6, nn = idx & 63;
        Ws1[nn][k] = __float2half_rn(W1[idx]);
    }
    for (int idx = t; idx < 64 * 32; idx += THREADS) {
        int k = idx >> 5, nn = idx & 31;
        Ws2[nn][k] = __float2half_rn(W2[idx]);
    }
    if (t < 64) b1s[t] = b1[t];
    if (t < 32) b2s[t] = b2[t];
    if (t < 48) Wos[t] = Wo[t];
    if (t == 0) *bosp = bo[0];
    {
        int tile0 = blockIdx.x;
        int base0 = tile0 * TILE;
        if (t < TILE) {
            int gi = base0 + t;
            usb[t] = (gi < n) ? user[gi] : 0;     // clamp OOB: loads stay safe
        } else {
            int s  = t - TILE;
            int gi = base0 + s;
            isb[s] = (gi < n) ? item[gi] : 0;
        }
    }
    __syncthreads();

    // issue cp.async wave for tile 0 (8 x 16B per thread)
    #pragma unroll
    for (int it = 0; it < 8; it++) {
        int r = rowg + it * 32, s = r >> 1, h = r & 1;
        int row = h ? isb[s] : usb[s];
        const float* src = (h ? mlp_i : mlp_u) + (size_t)row * 32 + lane8 * 4;
        uint32_t dst = (uint32_t)__cvta_generic_to_shared(&XsRaw[s][h * 32 + lane8 * 4]);
        cp_async16(dst, src);
    }
    asm volatile("cp.async.commit_group;\n");

    int cur = 0;
    for (int tile = blockIdx.x; tile < ntiles; tile += gridDim.x) {
        const int base = tile * TILE;
        const int nxt  = tile + gridDim.x;
        const bool has_nxt = nxt < ntiles;
        const int* us = usb + cur * TILE;
        const int* is = isb + cur * TILE;

        // ---- mf LDGs first: they fly while cp.async drains ----
        const int chunk = t & 3;
        const int sg    = t >> 2;
        const int s0 = sg, s1 = sg + 64;
        float4 a0 = ((const float4*)(mf_u + (size_t)us[s0] * 16))[chunk];
        float4 c0 = ((const float4*)(mf_i + (size_t)is[s0] * 16))[chunk];
        float4 a1 = ((const float4*)(mf_u + (size_t)us[s1] * 16))[chunk];
        float4 c1 = ((const float4*)(mf_i + (size_t)is[s1] * 16))[chunk];

        asm volatile("cp.async.wait_group 0;\n");
        __syncthreads();                       // B1: XsRaw ready; prev compute done

        // ---- convert XsRaw (fp32) -> Xs (fp16), conflict-free ----
        #pragma unroll
        for (int it = 0; it < 8; it++) {
            int r = rowg + it * 32, s = r >> 1, h = r & 1;
            float4 v = *(const float4*)&XsRaw[s][h * 32 + lane8 * 4];
            __half2 lo = __floats2half2_rn(v.x, v.y);
            __half2 hi = __floats2half2_rn(v.z, v.w);
            uint2 pk; pk.x = *(uint32_t*)&lo; pk.y = *(uint32_t*)&hi;
            *(uint2*)&Xs[s][h * 32 + lane8 * 4] = pk;
        }

        // ---- mf dot (exact fp32), quad shfl reduce ----
        {
            float w0 = Wos[4 * chunk + 0], w1 = Wos[4 * chunk + 1];
            float w2 = Wos[4 * chunk + 2], w3 = Wos[4 * chunk + 3];
            float acc0 = a0.x * c0.x * w0 + a0.y * c0.y * w1
                       + a0.z * c0.z * w2 + a0.w * c0.w * w3;
            float acc1 = a1.x * c1.x * w0 + a1.y * c1.y * w1
                       + a1.z * c1.z * w2 + a1.w * c1.w * w3;
            acc0 += __shfl_xor_sync(0xFFFFFFFFu, acc0, 1);
            acc0 += __shfl_xor_sync(0xFFFFFFFFu, acc0, 2);
            acc1 += __shfl_xor_sync(0xFFFFFFFFu, acc1, 1);
            acc1 += __shfl_xor_sync(0xFFFFFFFFu, acc1, 2);
            if (chunk == 0) { mfd[s0] = acc0; mfd[s1] = acc1; }
        }

        // ---- stage next tile's indices ----
        if (has_nxt) {
            int nbase = nxt * TILE;
            int* usn = usb + (cur ^ 1) * TILE;
            int* isn = isb + (cur ^ 1) * TILE;
            if (t < TILE) {
                int gi = nbase + t;
                usn[t] = (gi < n) ? user[gi] : 0;
            } else {
                int s  = t - TILE;
                int gi = nbase + s;
                isn[s] = (gi < n) ? item[gi] : 0;
            }
        }
        __syncthreads();                       // B2: Xs, mfd, next idx ready

        // ---- issue next tile's cp.async wave: overlaps the GEMM below ----
        if (has_nxt) {
            const int* usn = usb + (cur ^ 1) * TILE;
            const int* isn = isb + (cur ^ 1) * TILE;
            #pragma unroll
            for (int it = 0; it < 8; it++) {
                int r = rowg + it * 32, s = r >> 1, h = r & 1;
                int row = h ? isn[s] : usn[s];
                const float* src = (h ? mlp_i : mlp_u) + (size_t)row * 32 + lane8 * 4;
                uint32_t dst = (uint32_t)__cvta_generic_to_shared(&XsRaw[s][h * 32 + lane8 * 4]);
                cp_async16(dst, src);
            }
            asm volatile("cp.async.commit_group;\n");
        }

        // ---- GEMM pipeline (8 warps x 16 rows) ----
        const int warp  = t >> 5;
        const int lane  = t & 31;
        const int rbase = warp * 16;
        const int lr    = lane >> 2;
        const int lc    = lane & 3;

        float acc1[8][4];
        #pragma unroll
        for (int nn = 0; nn < 8; nn++)
            #pragma unroll
            for (int j = 0; j < 4; j++) acc1[nn][j] = 0.f;

        #pragma unroll
        for (int kt = 0; kt < 4; kt++) {
            uint32_t a[4];
            a[0] = *(const uint32_t*)&Xs[rbase + lr    ][kt * 16     + 2 * lc];
            a[1] = *(const uint32_t*)&Xs[rbase + lr + 8][kt * 16     + 2 * lc];
            a[2] = *(const uint32_t*)&Xs[rbase + lr    ][kt * 16 + 8 + 2 * lc];
            a[3] = *(const uint32_t*)&Xs[rbase + lr + 8][kt * 16 + 8 + 2 * lc];
            #pragma unroll
            for (int nn = 0; nn < 8; nn++) {
                uint32_t bb0 = *(const uint32_t*)&Ws1[nn * 8 + lr][kt * 16     + 2 * lc];
                uint32_t bb1 = *(const uint32_t*)&Ws1[nn * 8 + lr][kt * 16 + 8 + 2 * lc];
                mma16816(acc1[nn], a, bb0, bb1);
            }
        }

        uint32_t A2[4][4];
        #pragma unroll
        for (int nn = 0; nn < 8; nn++) {
            int   col = nn * 8 + 2 * lc;
            float bx = b1s[col], by = b1s[col + 1];
            float v0 = fmaxf(acc1[nn][0] + bx, 0.f);
            float v1 = fmaxf(acc1[nn][1] + by, 0.f);
            float v2 = fmaxf(acc1[nn][2] + bx, 0.f);
            float v3 = fmaxf(acc1[nn][3] + by, 0.f);
            __half2 lo = __floats2half2_rn(v0, v1);
            __half2 hi = __floats2half2_rn(v2, v3);
            int kt2 = nn >> 1, g = nn & 1;
            A2[kt2][g * 2 + 0] = *(uint32_t*)&lo;
            A2[kt2][g * 2 + 1] = *(uint32_t*)&hi;
        }

        float acc2[4][4];
        #pragma unroll
        for (int nn = 0; nn < 4; nn++)
            #pragma unroll
            for (int j = 0; j < 4; j++) acc2[nn][j] = 0.f;

        #pragma unroll
        for (int kt = 0; kt < 4; kt++) {
            #pragma unroll
            for (int nn = 0; nn < 4; nn++) {
                uint32_t bb0 = *(const uint32_t*)&Ws2[nn * 8 + lr][kt * 16     + 2 * lc];
                uint32_t bb1 = *(const uint32_t*)&Ws2[nn * 8 + lr][kt * 16 + 8 + 2 * lc];
                mma16816(acc2[nn], A2[kt], bb0, bb1);
            }
        }

        float s_lo = 0.f, s_hi = 0.f;
        #pragma unroll
        for (int nn = 0; nn < 4; nn++) {
            int   col = nn * 8 + 2 * lc;
            float bx = b2s[col], by = b2s[col + 1];
            float wx = Wos[16 + col], wy = Wos[16 + col + 1];
            s_lo += fmaxf(acc2[nn][0] + bx, 0.f) * wx + fmaxf(acc2[nn][1] + by, 0.f) * wy;
            s_hi += fmaxf(acc2[nn][2] + bx, 0.f) * wx + fmaxf(acc2[nn][3] + by, 0.f) * wy;
        }
        s_lo += __shfl_xor_sync(0xFFFFFFFFu, s_lo, 1);
        s_lo += __shfl_xor_sync(0xFFFFFFFFu, s_lo, 2);
        s_hi += __shfl_xor_sync(0xFFFFFFFFu, s_hi, 1);
        s_hi += __shfl_xor_sync(0xFFFFFFFFu, s_hi, 2);

        if (lc == 0) {
            int r0 = rbase + lr, r1 = rbase + lr + 8;
            if (base + r0 < n) out[base + r0] = s_lo + mfd[r0] + *bosp;
            if (base + r1 < n) out[base + r1] = s_hi + mfd[r1] + *bosp;
        }

        cur ^= 1;
    }
}

extern "C" void kernel_launch(void* const* d_in, const int* in_sizes, int n_in,
                              void* d_out, int out_size) {
    const int*   user  = (const int*)  d_in[0];
    const int*   item  = (const int*)  d_in[1];
    const float* mf_u  = (const float*)d_in[2];
    const float* mf_i  = (const float*)d_in[3];
    const float* mlp_u = (const float*)d_in[4];
    const float* mlp_i = (const float*)d_in[5];
    const float* W1    = (const float*)d_in[6];
    const float* b1    = (const float*)d_in[7];
    const float* W2    = (const float*)d_in[8];
    const float* b2    = (const float*)d_in[9];
    const float* Wo    = (const float*)d_in[10];
    const float* bo    = (const float*)d_in[11];
    float* out = (float*)d_out;

    int n = in_sizes[0];
    int ntiles = (n + TILE - 1) / TILE;

    // Persistent grid: one wave of 3 CTAs on each of 152 SMs; each CTA
    // pipelines ~18 tiles so steady-state overlap covers ~95% of gathers.
    int blocks = 456;
    if (blocks > ntiles) blocks = ntiles;

    cudaFuncSetAttribute(neumf_fused,
                         cudaFuncAttributeMaxDynamicSharedMemorySize, SMEM_TOTAL);
    neumf_fused<<<blocks, THREADS, SMEM_TOTAL>>>(user, item, mf_u, mf_i,
                                                 mlp_u, mlp_i, W1, b1, W2, b2,
                                                 Wo, bo, out, n, ntiles);
}

// round 16
// speedup vs baseline: 1.0005x; 1.0005x over previous
#include <cuda_runtime.h>
#include <cuda_fp16.h>
#include <stdint.h>

#define TILE    128
#define THREADS 256
#define XPAD    72   // halves per row: 64 data + 8 pad

// ---- dynamic smem layout (bytes) ----
#define OFF_XSRAW 0          // float[128][64]  = 32768
#define OFF_XS    32768      // half [128][72]  = 18432
#define OFF_WS1   51200      // half [64][72]   =  9216
#define OFF_WS2   60416      // half [32][72]   =  4608
#define OFF_B1    65024      // float[64]
#define OFF_B2    65280      // float[32]
#define OFF_WO    65408      // float[48]
#define OFF_MFD   65600      // float[128]
#define OFF_US    66112      // int[2][128]
#define OFF_IS    67136      // int[2][128]
#define OFF_BOS   68160      // float
#define SMEM_TOTAL 68224

__device__ __forceinline__ void mma16816(float c[4], const uint32_t a[4],
                                         uint32_t b0, uint32_t b1) {
    asm volatile(
        "mma.sync.aligned.m16n8k16.row.col.f32.f16.f16.f32 "
        "{%0,%1,%2,%3}, {%4,%5,%6,%7}, {%8,%9}, {%0,%1,%2,%3};"
        : "+f"(c[0]), "+f"(c[1]), "+f"(c[2]), "+f"(c[3])
        : "r"(a[0]), "r"(a[1]), "r"(a[2]), "r"(a[3]), "r"(b0), "r"(b1));
}

__device__ __forceinline__ void cp_async16(uint32_t dst, const void* src) {
    asm volatile("cp.async.cg.shared.global [%0], [%1], 16;\n" :: "r"(dst), "l"(src));
}

__global__ __launch_bounds__(THREADS, 3)   // 85-reg cap
void neumf_fused(const int* __restrict__ user, const int* __restrict__ item,
                 const float* __restrict__ mf_u, const float* __restrict__ mf_i,
                 const float* __restrict__ mlp_u, const float* __restrict__ mlp_i,
                 const float* __restrict__ W1, const float* __restrict__ b1,
                 const float* __restrict__ W2, const float* __restrict__ b2,
                 const float* __restrict__ Wo, const float* __restrict__ bo,
                 float* __restrict__ out, int n, int ntiles)
{
    extern __shared__ char smem[];
    float  (*XsRaw)[64]  = (float (*)[64]) (smem + OFF_XSRAW);
    __half (*Xs)[XPAD]   = (__half(*)[XPAD])(smem + OFF_XS);
    __half (*Ws1)[XPAD]  = (__half(*)[XPAD])(smem + OFF_WS1);
    __half (*Ws2)[XPAD]  = (__half(*)[XPAD])(smem + OFF_WS2);
    float* b1s  = (float*)(smem + OFF_B1);
    float* b2s  = (float*)(smem + OFF_B2);
    float* Wos  = (float*)(smem + OFF_WO);
    float* mfd  = (float*)(smem + OFF_MFD);
    int*   usb  = (int*)  (smem + OFF_US);
    int*   isb  = (int*)  (smem + OFF_IS);
    float* bosp = (float*)(smem + OFF_BOS);

    const int t     = threadIdx.x;
    const int lane8 = t & 7;       // float4 chunk within 128B row
    const int rowg  = t >> 3;      // 0..31

    // ---- Prologue: weights + tile-0 indices, then launch tile-0 cp.async ----
    for (int idx = t; idx < 64 * 64; idx += THREADS) {
        int k = idx >> 6, nn = idx & 63;
        Ws1[nn][k] = __float2half_rn(W1[idx]);
    }
    for (int idx = t; idx < 64 * 32; idx += THREADS) {
        int k = idx >> 5, nn = idx & 31;
        Ws2[nn][k] = __float2half_rn(W2[idx]);
    }
    if (t < 64) b1s[t] = b1[t];
    if (t < 32) b2s[t] = b2[t];
    if (t < 48) Wos[t] = Wo[t];
    if (t == 0) *bosp = bo[0];
    {
        int tile0 = blockIdx.x;
        int base0 = tile0 * TILE;
        if (t < TILE) {
            int gi = base0 + t;
            usb[t] = (gi < n) ? user[gi] : 0;     // clamp OOB: loads stay safe
        } else {
            int s  = t - TILE;
            int gi = base0 + s;
            isb[s] = (gi < n) ? item[gi] : 0;
        }
    }
    __syncthreads();

    // issue cp.async wave for tile 0 (8 x 16B per thread)
    #pragma unroll
    for (int it = 0; it < 8; it++) {
        int r = rowg + it * 32, s = r >> 1, h = r & 1;
        int row = h ? isb[s] : usb[s];
        const float* src = (h ? mlp_i : mlp_u) + (size_t)row * 32 + lane8 * 4;
        uint32_t dst = (uint32_t)__cvta_generic_to_shared(&XsRaw[s][h * 32 + lane8 * 4]);
        cp_async16(dst, src);
    }
    asm volatile("cp.async.commit_group;\n");

    int cur = 0;
    for (int tile = blockIdx.x; tile < ntiles; tile += gridDim.x) {
        const int base = tile * TILE;
        const int nxt  = tile + gridDim.x;
        const bool has_nxt = nxt < ntiles;
        const int* us = usb + cur * TILE;
        const int* is = isb + cur * TILE;

        // ---- mf LDGs first: they fly while cp.async drains ----
        const int chunk = t & 3;
        const int sg    = t >> 2;
        const int s0 = sg, s1 = sg + 64;
        float4 a0 = ((const float4*)(mf_u + (size_t)us[s0] * 16))[chunk];
        float4 c0 = ((const float4*)(mf_i + (size_t)is[s0] * 16))[chunk];
        float4 a1 = ((const float4*)(mf_u + (size_t)us[s1] * 16))[chunk];
        float4 c1 = ((const float4*)(mf_i + (size_t)is[s1] * 16))[chunk];

        asm volatile("cp.async.wait_group 0;\n");
        __syncthreads();                       // B1: XsRaw ready; prev compute done

        // ---- convert XsRaw (fp32) -> Xs (fp16), conflict-free ----
        #pragma unroll
        for (int it = 0; it < 8; it++) {
            int r = rowg + it * 32, s = r >> 1, h = r & 1;
            float4 v = *(const float4*)&XsRaw[s][h * 32 + lane8 * 4];
            __half2 lo = __floats2half2_rn(v.x, v.y);
            __half2 hi = __floats2half2_rn(v.z, v.w);
            uint2 pk; pk.x = *(uint32_t*)&lo; pk.y = *(uint32_t*)&hi;
            *(uint2*)&Xs[s][h * 32 + lane8 * 4] = pk;
        }

        // ---- mf dot (exact fp32), quad shfl reduce ----
        {
            float w0 = Wos[4 * chunk + 0], w1 = Wos[4 * chunk + 1];
            float w2 = Wos[4 * chunk + 2], w3 = Wos[4 * chunk + 3];
            float acc0 = a0.x * c0.x * w0 + a0.y * c0.y * w1
                       + a0.z * c0.z * w2 + a0.w * c0.w * w3;
            float acc1 = a1.x * c1.x * w0 + a1.y * c1.y * w1
                       + a1.z * c1.z * w2 + a1.w * c1.w * w3;
            acc0 += __shfl_xor_sync(0xFFFFFFFFu, acc0, 1);
            acc0 += __shfl_xor_sync(0xFFFFFFFFu, acc0, 2);
            acc1 += __shfl_xor_sync(0xFFFFFFFFu, acc1, 1);
            acc1 += __shfl_xor_sync(0xFFFFFFFFu, acc1, 2);
            if (chunk == 0) { mfd[s0] = acc0; mfd[s1] = acc1; }
        }

        // ---- stage next tile's indices ----
        if (has_nxt) {
            int nbase = nxt * TILE;
            int* usn = usb + (cur ^ 1) * TILE;
            int* isn = isb + (cur ^ 1) * TILE;
            if (t < TILE) {
                int gi = nbase + t;
                usn[t] = (gi < n) ? user[gi] : 0;
            } else {
                int s  = t - TILE;
                int gi = nbase + s;
                isn[s] = (gi < n) ? item[gi] : 0;
            }
        }
        __syncthreads();                       // B2: Xs, mfd, next idx ready

        // ---- issue next tile's cp.async wave: overlaps the GEMM below ----
        if (has_nxt) {
            const int* usn = usb + (cur ^ 1) * TILE;
            const int* isn = isb + (cur ^ 1) * TILE;
            #pragma unroll
            for (int it = 0; it < 8; it++) {
                int r = rowg + it * 32, s = r >> 1, h = r & 1;
                int row = h ? isn[s] : usn[s];
                const float* src = (h ? mlp_i : mlp_u) + (size_t)row * 32 + lane8 * 4;
                uint32_t dst = (uint32_t)__cvta_generic_to_shared(&XsRaw[s][h * 32 + lane8 * 4]);
                cp_async16(dst, src);
            }
            asm volatile("cp.async.commit_group;\n");
        }

        // ---- GEMM pipeline (8 warps x 16 rows) ----
        const int warp  = t >> 5;
        const int lane  = t & 31;
        const int rbase = warp * 16;
        const int lr    = lane >> 2;
        const int lc    = lane & 3;

        float acc1[8][4];
        #pragma unroll
        for (int nn = 0; nn < 8; nn++)
            #pragma unroll
            for (int j = 0; j < 4; j++) acc1[nn][j] = 0.f;

        #pragma unroll
        for (int kt = 0; kt < 4; kt++) {
            uint32_t a[4];
            a[0] = *(const uint32_t*)&Xs[rbase + lr    ][kt * 16     + 2 * lc];
            a[1] = *(const uint32_t*)&Xs[rbase + lr + 8][kt * 16     + 2 * lc];
            a[2] = *(const uint32_t*)&Xs[rbase + lr    ][kt * 16 + 8 + 2 * lc];
            a[3] = *(const uint32_t*)&Xs[rbase + lr + 8][kt * 16 + 8 + 2 * lc];
            #pragma unroll
            for (int nn = 0; nn < 8; nn++) {
                uint32_t bb0 = *(const uint32_t*)&Ws1[nn * 8 + lr][kt * 16     + 2 * lc];
                uint32_t bb1 = *(const uint32_t*)&Ws1[nn * 8 + lr][kt * 16 + 8 + 2 * lc];
                mma16816(acc1[nn], a, bb0, bb1);
            }
        }

        uint32_t A2[4][4];
        #pragma unroll
        for (int nn = 0; nn < 8; nn++) {
            int   col = nn * 8 + 2 * lc;
            float bx = b1s[col], by = b1s[col + 1];
            float v0 = fmaxf(acc1[nn][0] + bx, 0.f);
            float v1 = fmaxf(acc1[nn][1] + by, 0.f);
            float v2 = fmaxf(acc1[nn][2] + bx, 0.f);
            float v3 = fmaxf(acc1[nn][3] + by, 0.f);
            __half2 lo = __floats2half2_rn(v0, v1);
            __half2 hi = __floats2half2_rn(v2, v3);
            int kt2 = nn >> 1, g = nn & 1;
            A2[kt2][g * 2 + 0] = *(uint32_t*)&lo;
            A2[kt2][g * 2 + 1] = *(uint32_t*)&hi;
        }

        float acc2[4][4];
        #pragma unroll
        for (int nn = 0; nn < 4; nn++)
            #pragma unroll
            for (int j = 0; j < 4; j++) acc2[nn][j] = 0.f;

        #pragma unroll
        for (int kt = 0; kt < 4; kt++) {
            #pragma unroll
            for (int nn = 0; nn < 4; nn++) {
                uint32_t bb0 = *(const uint32_t*)&Ws2[nn * 8 + lr][kt * 16     + 2 * lc];
                uint32_t bb1 = *(const uint32_t*)&Ws2[nn * 8 + lr][kt * 16 + 8 + 2 * lc];
                mma16816(acc2[nn], A2[kt], bb0, bb1);
            }
        }

        float s_lo = 0.f, s_hi = 0.f;
        #pragma unroll
        for (int nn = 0; nn < 4; nn++) {
            int   col = nn * 8 + 2 * lc;
            float bx = b2s[col], by = b2s[col + 1];
            float wx = Wos[16 + col], wy = Wos[16 + col + 1];
            s_lo += fmaxf(acc2[nn][0] + bx, 0.f) * wx + fmaxf(acc2[nn][1] + by, 0.f) * wy;
            s_hi += fmaxf(acc2[nn][2] + bx, 0.f) * wx + fmaxf(acc2[nn][3] + by, 0.f) * wy;
        }
        s_lo += __shfl_xor_sync(0xFFFFFFFFu, s_lo, 1);
        s_lo += __shfl_xor_sync(0xFFFFFFFFu, s_lo, 2);
        s_hi += __shfl_xor_sync(0xFFFFFFFFu, s_hi, 1);
        s_hi += __shfl_xor_sync(0xFFFFFFFFu, s_hi, 2);

        if (lc == 0) {
            int r0 = rbase + lr, r1 = rbase + lr + 8;
            if (base + r0 < n) out[base + r0] = s_lo + mfd[r0] + *bosp;
            if (base + r1 < n) out[base + r1] = s_hi + mfd[r1] + *bosp;
        }

        cur ^= 1;
    }
}

extern "C" void kernel_launch(void* const* d_in, const int* in_sizes, int n_in,
                              void* d_out, int out_size) {
    const int*   user  = (const int*)  d_in[0];
    const int*   item  = (const int*)  d_in[1];
    const float* mf_u  = (const float*)d_in[2];
    const float* mf_i  = (const float*)d_in[3];
    const float* mlp_u = (const float*)d_in[4];
    const float* mlp_i = (const float*)d_in[5];
    const float* W1    = (const float*)d_in[6];
    const float* b1    = (const float*)d_in[7];
    const float* W2    = (const float*)d_in[8];
    const float* b2    = (const float*)d_in[9];
    const float* Wo    = (const float*)d_in[10];
    const float* bo    = (const float*)d_in[11];
    float* out = (float*)d_out;

    int n = in_sizes[0];
    int ntiles = (n + TILE - 1) / TILE;

    // Persistent grid: one wave of 3 CTAs on each of 152 SMs; each CTA
    // pipelines ~18 tiles so steady-state overlap covers ~95% of gathers.
    int blocks = 456;
    if (blocks > ntiles) blocks = ntiles;

    cudaFuncSetAttribute(neumf_fused,
                         cudaFuncAttributeMaxDynamicSharedMemorySize, SMEM_TOTAL);
    neumf_fused<<<blocks, THREADS, SMEM_TOTAL>>>(user, item, mf_u, mf_i,
                                                 mlp_u, mlp_i, W1, b1, W2, b2,
                                                 Wo, bo, out, n, ntiles);
}

// round 17
// speedup vs baseline: 1.0010x; 1.0005x over previous
#include <cuda_runtime.h>
#include <cuda_fp16.h>
#include <stdint.h>

#define TILE    128
#define THREADS 256
#define XPAD    72   // halves per row: 64 data + 8 pad

// ---- dynamic smem layout (bytes) ----
#define OFF_XSRAW 0          // float[128][64]  = 32768
#define OFF_XS    32768      // half [128][72]  = 18432
#define OFF_WS1   51200      // half [64][72]   =  9216
#define OFF_WS2   60416      // half [32][72]   =  4608
#define OFF_B1    65024      // float[64]
#define OFF_B2    65280      // float[32]
#define OFF_WO    65408      // float[48]
#define OFF_MFD   65600      // float[128]
#define OFF_US    66112      // int[2][128]
#define OFF_IS    67136      // int[2][128]
#define OFF_BOS   68160      // float
#define SMEM_TOTAL 68224

__device__ __forceinline__ void mma16816(float c[4], const uint32_t a[4],
                                         uint32_t b0, uint32_t b1) {
    asm volatile(
        "mma.sync.aligned.m16n8k16.row.col.f32.f16.f16.f32 "
        "{%0,%1,%2,%3}, {%4,%5,%6,%7}, {%8,%9}, {%0,%1,%2,%3};"
        : "+f"(c[0]), "+f"(c[1]), "+f"(c[2]), "+f"(c[3])
        : "r"(a[0]), "r"(a[1]), "r"(a[2]), "r"(a[3]), "r"(b0), "r"(b1));
}

__device__ __forceinline__ void cp_async16(uint32_t dst, const void* src) {
    asm volatile("cp.async.cg.shared.global [%0], [%1], 16;\n" :: "r"(dst), "l"(src));
}

__global__ __launch_bounds__(THREADS, 3)   // 85-reg cap
void neumf_fused(const int* __restrict__ user, const int* __restrict__ item,
                 const float* __restrict__ mf_u, const float* __restrict__ mf_i,
                 const float* __restrict__ mlp_u, const float* __restrict__ mlp_i,
                 const float* __restrict__ W1, const float* __restrict__ b1,
                 const float* __restrict__ W2, const float* __restrict__ b2,
                 const float* __restrict__ Wo, const float* __restrict__ bo,
                 float* __restrict__ out, int n, int ntiles)
{
    extern __shared__ char smem[];
    float  (*XsRaw)[64]  = (float (*)[64]) (smem + OFF_XSRAW);
    __half (*Xs)[XPAD]   = (__half(*)[XPAD])(smem + OFF_XS);
    __half (*Ws1)[XPAD]  = (__half(*)[XPAD])(smem + OFF_WS1);
    __half (*Ws2)[XPAD]  = (__half(*)[XPAD])(smem + OFF_WS2);
    float* b1s  = (float*)(smem + OFF_B1);
    float* b2s  = (float*)(smem + OFF_B2);
    float* Wos  = (float*)(smem + OFF_WO);
    float* mfd  = (float*)(smem + OFF_MFD);
    int*   usb  = (int*)  (smem + OFF_US);
    int*   isb  = (int*)  (smem + OFF_IS);
    float* bosp = (float*)(smem + OFF_BOS);

    const int t     = threadIdx.x;
    const int lane8 = t & 7;       // float4 chunk within 128B row
    const int rowg  = t >> 3;      // 0..31

    // ---- Prologue: weights + tile-0 indices, then launch tile-0 cp.async ----
    for (int idx = t; idx < 64 * 64; idx += THREADS) {
        int k = idx >> 6, nn = idx & 63;
        Ws1[nn][k] = __float2half_rn(W1[idx]);
    }
    for (int idx = t; idx < 64 * 32; idx += THREADS) {
        int k = idx >> 5, nn = idx & 31;
        Ws2[nn][k] = __float2half_rn(W2[idx]);
    }
    if (t < 64) b1s[t] = b1[t];
    if (t < 32) b2s[t] = b2[t];
    if (t < 48) Wos[t] = Wo[t];
    if (t == 0) *bosp = bo[0];
    {
        int tile0 = blockIdx.x;
        int base0 = tile0 * TILE;
        if (t < TILE) {
            int gi = base0 + t;
            usb[t] = (gi < n) ? user[gi] : 0;     // clamp OOB: loads stay safe
        } else {
            int s  = t - TILE;
            int gi = base0 + s;
            isb[s] = (gi < n) ? item[gi] : 0;
        }
    }
    __syncthreads();

    // issue cp.async wave for tile 0 (8 x 16B per thread)
    #pragma unroll
    for (int it = 0; it < 8; it++) {
        int r = rowg + it * 32, s = r >> 1, h = r & 1;
        int row = h ? isb[s] : usb[s];
        const float* src = (h ? mlp_i : mlp_u) + (size_t)row * 32 + lane8 * 4;
        uint32_t dst = (uint32_t)__cvta_generic_to_shared(&XsRaw[s][h * 32 + lane8 * 4]);
        cp_async16(dst, src);
    }
    asm volatile("cp.async.commit_group;\n");

    int cur = 0;
    for (int tile = blockIdx.x; tile < ntiles; tile += gridDim.x) {
        const int base = tile * TILE;
        const int nxt  = tile + gridDim.x;
        const bool has_nxt = nxt < ntiles;
        const int* us = usb + cur * TILE;
        const int* is = isb + cur * TILE;

        // ---- mf LDGs first: they fly while cp.async drains ----
        const int chunk = t & 3;
        const int sg    = t >> 2;
        const int s0 = sg, s1 = sg + 64;
        float4 a0 = ((const float4*)(mf_u + (size_t)us[s0] * 16))[chunk];
        float4 c0 = ((const float4*)(mf_i + (size_t)is[s0] * 16))[chunk];
        float4 a1 = ((const float4*)(mf_u + (size_t)us[s1] * 16))[chunk];
        float4 c1 = ((const float4*)(mf_i + (size_t)is[s1] * 16))[chunk];

        asm volatile("cp.async.wait_group 0;\n");
        __syncthreads();                       // B1: XsRaw ready; prev compute done

        // ---- convert XsRaw (fp32) -> Xs (fp16), conflict-free ----
        #pragma unroll
        for (int it = 0; it < 8; it++) {
            int r = rowg + it * 32, s = r >> 1, h = r & 1;
            float4 v = *(const float4*)&XsRaw[s][h * 32 + lane8 * 4];
            __half2 lo = __floats2half2_rn(v.x, v.y);
            __half2 hi = __floats2half2_rn(v.z, v.w);
            uint2 pk; pk.x = *(uint32_t*)&lo; pk.y = *(uint32_t*)&hi;
            *(uint2*)&Xs[s][h * 32 + lane8 * 4] = pk;
        }

        // ---- mf dot (exact fp32), quad shfl reduce ----
        {
            float w0 = Wos[4 * chunk + 0], w1 = Wos[4 * chunk + 1];
            float w2 = Wos[4 * chunk + 2], w3 = Wos[4 * chunk + 3];
            float acc0 = a0.x * c0.x * w0 + a0.y * c0.y * w1
                       + a0.z * c0.z * w2 + a0.w * c0.w * w3;
            float acc1 = a1.x * c1.x * w0 + a1.y * c1.y * w1
                       + a1.z * c1.z * w2 + a1.w * c1.w * w3;
            acc0 += __shfl_xor_sync(0xFFFFFFFFu, acc0, 1);
            acc0 += __shfl_xor_sync(0xFFFFFFFFu, acc0, 2);
            acc1 += __shfl_xor_sync(0xFFFFFFFFu, acc1, 1);
            acc1 += __shfl_xor_sync(0xFFFFFFFFu, acc1, 2);
            if (chunk == 0) { mfd[s0] = acc0; mfd[s1] = acc1; }
        }

        // ---- stage next tile's indices ----
        if (has_nxt) {
            int nbase = nxt * TILE;
            int* usn = usb + (cur ^ 1) * TILE;
            int* isn = isb + (cur ^ 1) * TILE;
            if (t < TILE) {
                int gi = nbase + t;
                usn[t] = (gi < n) ? user[gi] : 0;
            } else {
                int s  = t - TILE;
                int gi = nbase + s;
                isn[s] = (gi < n) ? item[gi] : 0;
            }
        }
        __syncthreads();                       // B2: Xs, mfd, next idx ready

        // ---- issue next tile's cp.async wave: overlaps the GEMM below ----
        if (has_nxt) {
            const int* usn = usb + (cur ^ 1) * TILE;
            const int* isn = isb + (cur ^ 1) * TILE;
            #pragma unroll
            for (int it = 0; it < 8; it++) {
                int r = rowg + it * 32, s = r >> 1, h = r & 1;
                int row = h ? isn[s] : usn[s];
                const float* src = (h ? mlp_i : mlp_u) + (size_t)row * 32 + lane8 * 4;
                uint32_t dst = (uint32_t)__cvta_generic_to_shared(&XsRaw[s][h * 32 + lane8 * 4]);
                cp_async16(dst, src);
            }
            asm volatile("cp.async.commit_group;\n");
        }

        // ---- GEMM pipeline (8 warps x 16 rows) ----
        const int warp  = t >> 5;
        const int lane  = t & 31;
        const int rbase = warp * 16;
        const int lr    = lane >> 2;
        const int lc    = lane & 3;

        float acc1[8][4];
        #pragma unroll
        for (int nn = 0; nn < 8; nn++)
            #pragma unroll
            for (int j = 0; j < 4; j++) acc1[nn][j] = 0.f;

        #pragma unroll
        for (int kt = 0; kt < 4; kt++) {
            uint32_t a[4];
            a[0] = *(const uint32_t*)&Xs[rbase + lr    ][kt * 16     + 2 * lc];
            a[1] = *(const uint32_t*)&Xs[rbase + lr + 8][kt * 16     + 2 * lc];
            a[2] = *(const uint32_t*)&Xs[rbase + lr    ][kt * 16 + 8 + 2 * lc];
            a[3] = *(const uint32_t*)&Xs[rbase + lr + 8][kt * 16 + 8 + 2 * lc];
            #pragma unroll
            for (int nn = 0; nn < 8; nn++) {
                uint32_t bb0 = *(const uint32_t*)&Ws1[nn * 8 + lr][kt * 16     + 2 * lc];
                uint32_t bb1 = *(const uint32_t*)&Ws1[nn * 8 + lr][kt * 16 + 8 + 2 * lc];
                mma16816(acc1[nn], a, bb0, bb1);
            }
        }

        uint32_t A2[4][4];
        #pragma unroll
        for (int nn = 0; nn < 8; nn++) {
            int   col = nn * 8 + 2 * lc;
            float bx = b1s[col], by = b1s[col + 1];
            float v0 = fmaxf(acc1[nn][0] + bx, 0.f);
            float v1 = fmaxf(acc1[nn][1] + by, 0.f);
            float v2 = fmaxf(acc1[nn][2] + bx, 0.f);
            float v3 = fmaxf(acc1[nn][3] + by, 0.f);
            __half2 lo = __floats2half2_rn(v0, v1);
            __half2 hi = __floats2half2_rn(v2, v3);
            int kt2 = nn >> 1, g = nn & 1;
            A2[kt2][g * 2 + 0] = *(uint32_t*)&lo;
            A2[kt2][g * 2 + 1] = *(uint32_t*)&hi;
        }

        float acc2[4][4];
        #pragma unroll
        for (int nn = 0; nn < 4; nn++)
            #pragma unroll
            for (int j = 0; j < 4; j++) acc2[nn][j] = 0.f;

        #pragma unroll
        for (int kt = 0; kt < 4; kt++) {
            #pragma unroll
            for (int nn = 0; nn < 4; nn++) {
                uint32_t bb0 = *(const uint32_t*)&Ws2[nn * 8 + lr][kt * 16     + 2 * lc];
                uint32_t bb1 = *(const uint32_t*)&Ws2[nn * 8 + lr][kt * 16 + 8 + 2 * lc];
                mma16816(acc2[nn], A2[kt], bb0, bb1);
            }
        }

        float s_lo = 0.f, s_hi = 0.f;
        #pragma unroll
        for (int nn = 0; nn < 4; nn++) {
            int   col = nn * 8 + 2 * lc;
            float bx = b2s[col], by = b2s[col + 1];
            float wx = Wos[16 + col], wy = Wos[16 + col + 1];
            s_lo += fmaxf(acc2[nn][0] + bx, 0.f) * wx + fmaxf(acc2[nn][1] + by, 0.f) * wy;
            s_hi += fmaxf(acc2[nn][2] + bx, 0.f) * wx + fmaxf(acc2[nn][3] + by, 0.f) * wy;
        }
        s_lo += __shfl_xor_sync(0xFFFFFFFFu, s_lo, 1);
        s_lo += __shfl_xor_sync(0xFFFFFFFFu, s_lo, 2);
        s_hi += __shfl_xor_sync(0xFFFFFFFFu, s_hi, 1);
        s_hi += __shfl_xor_sync(0xFFFFFFFFu, s_hi, 2);

        if (lc == 0) {
            int r0 = rbase + lr, r1 = rbase + lr + 8;
            if (base + r0 < n) out[base + r0] = s_lo + mfd[r0] + *bosp;
            if (base + r1 < n) out[base + r1] = s_hi + mfd[r1] + *bosp;
        }

        cur ^= 1;
    }
}

extern "C" void kernel_launch(void* const* d_in, const int* in_sizes, int n_in,
                              void* d_out, int out_size) {
    const int*   user  = (const int*)  d_in[0];
    const int*   item  = (const int*)  d_in[1];
    const float* mf_u  = (const float*)d_in[2];
    const float* mf_i  = (const float*)d_in[3];
    const float* mlp_u = (const float*)d_in[4];
    const float* mlp_i = (const float*)d_in[5];
    const float* W1    = (const float*)d_in[6];
    const float* b1    = (const float*)d_in[7];
    const float* W2    = (const float*)d_in[8];
    const float* b2    = (const float*)d_in[9];
    const float* Wo    = (const float*)d_in[10];
    const float* bo    = (const float*)d_in[11];
    float* out = (float*)d_out;

    int n = in_sizes[0];
    int ntiles = (n + TILE - 1) / TILE;

    // Persistent grid: one wave of 3 CTAs on each of 152 SMs; each CTA
    // pipelines ~18 tiles so steady-state overlap covers ~95% of gathers.
    int blocks = 456;
    if (blocks > ntiles) blocks = ntiles;

    cudaFuncSetAttribute(neumf_fused,
                         cudaFuncAttributeMaxDynamicSharedMemorySize, SMEM_TOTAL);
    neumf_fused<<<blocks, THREADS, SMEM_TOTAL>>>(user, item, mf_u, mf_i,
                                                 mlp_u, mlp_i, W1, b1, W2, b2,
                                                 Wo, bo, out, n, ntiles);
}